// round 15
// baseline (speedup 1.0000x reference)
#include <cuda_runtime.h>
#include <cuda_bf16.h>
#include <cuda_fp16.h>
#include <cstdint>

typedef unsigned int uint;

#define MAX_N  100000
#define TILE_E 64
#define ITER   8      // edge tiles per block

// Interleaved per-node table, 768 bytes:
//  [0:256)    W src-half: 128 fp16
//  [256:384)  A src-half: 128 e4m3
//  [384:640)  W tgt-half: 128 fp16
//  [640:768)  A tgt-half: 128 e4m3
static __device__ unsigned char g_proj[(size_t)MAX_N * 768];
static __device__ unsigned char g_A2f8[64 * 128];     // A2^T as [n][k] e4m3
static __device__ float         g_ab2[64];
static __device__ unsigned char g_Wswz[2][256 * 256]; // pre-swizzled fp16 weight images

__device__ __forceinline__ unsigned short pack_e4m3_2(float f0, float f1) {
    unsigned short r;
    asm("cvt.rn.satfinite.e4m3x2.f32 %0, %2, %1;" : "=h"(r) : "f"(f0), "f"(f1));
    return r;
}

__device__ __forceinline__ unsigned short cvt_f16x2_e4m3x2(uint h2) {
    unsigned short r;
    asm("cvt.rn.satfinite.e4m3x2.f16x2 %0, %1;" : "=h"(r) : "r"(h2));
    return r;
}

__device__ __forceinline__ void unpack_e4m3_4(uint v, uint& h01, uint& h23) {
    asm("{\n\t.reg .b16 lo, hi;\n\t"
        "mov.b32 {lo, hi}, %2;\n\t"
        "cvt.rn.f16x2.e4m3x2 %0, lo;\n\t"
        "cvt.rn.f16x2.e4m3x2 %1, hi;\n\t}"
        : "=r"(h01), "=r"(h23) : "r"(v));
}

// ------------------------------------------------------------- prep ---------
__global__ void __launch_bounds__(256)
a2prep_kernel(const float* __restrict__ A2, const float* __restrict__ ab2)
{
    const int t = threadIdx.x;
    const int n = t >> 2, kc = t & 3;
    #pragma unroll
    for (int j = 0; j < 8; ++j) {
        int k = kc * 32 + j * 4;
        float f0 = A2[(size_t)(k + 0) * 64 + n];
        float f1 = A2[(size_t)(k + 1) * 64 + n];
        float f2 = A2[(size_t)(k + 2) * 64 + n];
        float f3 = A2[(size_t)(k + 3) * 64 + n];
        unsigned short lo = pack_e4m3_2(f0, f1);
        unsigned short hi = pack_e4m3_2(f2, f3);
        uint v;
        asm("mov.b32 %0, {%1, %2};" : "=r"(v) : "h"(lo), "h"(hi));
        *(uint*)&g_A2f8[n * 128 + k] = v;
    }
    if (t < 64) g_ab2[t] = ab2[t];
}

__global__ void __launch_bounds__(256)
wprep_kernel(const float* __restrict__ W1, const float* __restrict__ A1)
{
    int c = blockIdx.x * 256 + threadIdx.x;
    int img = c >> 8, col = c & 255;
    const float* __restrict__ Wm = img ? A1 : W1;
    int koff = (col >= 128) ? 128 : 0;
    int cc = col - koff;
    unsigned char* dst = g_Wswz[img] + col * 256;
    #pragma unroll 4
    for (int k = 0; k < 128; k += 2) {
        float f0 = Wm[(size_t)(koff + k)     * 128 + cc];
        float f1 = Wm[(size_t)(koff + k + 1) * 128 + cc];
        __half2 h = __floats2half2_rn(f0, f1);
        int byte = (2 * k) ^ (16 * ((col >> 2) & 7));
        *(uint*)(dst + byte) = *(uint*)&h;
    }
}

// ---------------------------------------------------------------- stage 1 ---
#define S1_WS     0
#define S1_AS     69632
#define S1_TOTAL  87040

__global__ void __launch_bounds__(256, 2)
precompute_kernel(const float* __restrict__ emb, int N)
{
    extern __shared__ char sm[];
    char* Ws = sm + S1_WS;
    char* As = sm + S1_AS;

    const int t    = threadIdx.x;
    const int base = blockIdx.x * 64;

    #pragma unroll
    for (int j = 0; j < 8; ++j) {
        int idx = t + 256 * j;
        int row = idx >> 5, q = idx & 31;
        int n = base + row; if (n >= N) n = N - 1;
        float4 v = ((const float4*)emb)[(size_t)n * 32 + q];
        __half2 h0 = __floats2half2_rn(v.x, v.y);
        __half2 h1 = __floats2half2_rn(v.z, v.w);
        uint2 st; st.x = *(uint*)&h0; st.y = *(uint*)&h1;
        *(uint2*)(As + row * 272 + q * 8) = st;
    }

    const int w = t >> 5, l = t & 31;
    const int wm = w >> 2, wn = w & 3;
    const int rbase = wm * 32;
    const int cbase = wn * 64;
    const int lq = l >> 2, lr = l & 3;
    const int m  = l >> 3;

    unsigned wsBase = (unsigned)__cvta_generic_to_shared(Ws);
    unsigned asBase = (unsigned)__cvta_generic_to_shared(As);

    const int arow_off = (m & 1) * 8 + (l & 7);
    const int aksel    = (m >> 1) * 16;
    const int brow_off = (m >> 1) * 8 + (l & 7);
    const int bksel    = (m & 1) * 16;

    #pragma unroll 1
    for (int img = 0; img < 2; ++img) {
        __syncthreads();
        {
            const unsigned char* src = g_Wswz[img];
            #pragma unroll
            for (int j = 0; j < 16; ++j) {
                int idx = t + 256 * j;
                int col = idx >> 4, chunk = idx & 15;
                uint4 v = *(const uint4*)(src + col * 256 + chunk * 16);
                *(uint4*)(Ws + col * 272 + chunk * 16) = v;
            }
        }
        __syncthreads();

        float c[2][8][4];
        #pragma unroll
        for (int mt = 0; mt < 2; ++mt)
            #pragma unroll
            for (int nt = 0; nt < 8; ++nt)
                #pragma unroll
                for (int i = 0; i < 4; ++i) c[mt][nt][i] = 0.f;

        #pragma unroll
        for (int ks = 0; ks < 8; ++ks) {
            uint a[2][4];
            #pragma unroll
            for (int mt = 0; mt < 2; ++mt) {
                int row = rbase + mt * 16 + arow_off;
                unsigned addr = asBase + (unsigned)(row * 272 + ks * 32 + aksel);
                asm volatile("ldmatrix.sync.aligned.m8n8.x4.shared.b16 {%0,%1,%2,%3}, [%4];"
                             : "=r"(a[mt][0]), "=r"(a[mt][1]), "=r"(a[mt][2]), "=r"(a[mt][3])
                             : "r"(addr));
            }
            #pragma unroll
            for (int nt2 = 0; nt2 < 4; ++nt2) {
                int row = cbase + nt2 * 16 + brow_off;
                int byte = (ks * 32 + bksel) ^ (16 * ((row >> 2) & 7));
                unsigned addr = wsBase + (unsigned)(row * 272 + byte);
                uint b0, b1, b2, b3;
                asm volatile("ldmatrix.sync.aligned.m8n8.x4.shared.b16 {%0,%1,%2,%3}, [%4];"
                             : "=r"(b0), "=r"(b1), "=r"(b2), "=r"(b3) : "r"(addr));
                #pragma unroll
                for (int mt = 0; mt < 2; ++mt) {
                    asm volatile("mma.sync.aligned.m16n8k16.row.col.f32.f16.f16.f32 "
                                 "{%0,%1,%2,%3},{%4,%5,%6,%7},{%8,%9},{%0,%1,%2,%3};"
                                 : "+f"(c[mt][2*nt2][0]), "+f"(c[mt][2*nt2][1]),
                                   "+f"(c[mt][2*nt2][2]), "+f"(c[mt][2*nt2][3])
                                 : "r"(a[mt][0]), "r"(a[mt][1]), "r"(a[mt][2]), "r"(a[mt][3]),
                                   "r"(b0), "r"(b1));
                    asm volatile("mma.sync.aligned.m16n8k16.row.col.f32.f16.f16.f32 "
                                 "{%0,%1,%2,%3},{%4,%5,%6,%7},{%8,%9},{%0,%1,%2,%3};"
                                 : "+f"(c[mt][2*nt2+1][0]), "+f"(c[mt][2*nt2+1][1]),
                                   "+f"(c[mt][2*nt2+1][2]), "+f"(c[mt][2*nt2+1][3])
                                 : "r"(a[mt][0]), "r"(a[mt][1]), "r"(a[mt][2]), "r"(a[mt][3]),
                                   "r"(b2), "r"(b3));
                }
            }
        }
        __syncthreads();

        if (img == 0) {
            #pragma unroll
            for (int mt = 0; mt < 2; ++mt) {
                #pragma unroll
                for (int nt = 0; nt < 8; ++nt) {
                    int r  = rbase + mt * 16 + lq;
                    int cc = cbase + nt * 8 + 2 * lr;
                    __half2 h01 = __floats2half2_rn(c[mt][nt][0], c[mt][nt][1]);
                    __half2 h23 = __floats2half2_rn(c[mt][nt][2], c[mt][nt][3]);
                    *(uint*)(sm + r * 528 + cc * 2)       = *(uint*)&h01;
                    *(uint*)(sm + (r + 8) * 528 + cc * 2) = *(uint*)&h23;
                }
            }
            __syncthreads();
            #pragma unroll
            for (int j = 0; j < 8; ++j) {
                int idx = t + 256 * j;
                int row = idx >> 5, s = idx & 31;
                if (base + row < N) {
                    uint4 v = *(uint4*)(sm + row * 528 + s * 16);
                    int dst = (s < 16) ? s * 16 : 384 + (s - 16) * 16;
                    *(uint4*)&g_proj[(size_t)(base + row) * 768 + dst] = v;
                }
            }
        } else {
            #pragma unroll
            for (int mt = 0; mt < 2; ++mt) {
                #pragma unroll
                for (int nt = 0; nt < 8; ++nt) {
                    int r  = rbase + mt * 16 + lq;
                    int cc = cbase + nt * 8 + 2 * lr;
                    *(unsigned short*)(sm + r * 272 + cc)       = pack_e4m3_2(c[mt][nt][0], c[mt][nt][1]);
                    *(unsigned short*)(sm + (r + 8) * 272 + cc) = pack_e4m3_2(c[mt][nt][2], c[mt][nt][3]);
                }
            }
            __syncthreads();
            #pragma unroll
            for (int j = 0; j < 4; ++j) {
                int idx = t + 256 * j;
                int row = idx >> 4, s = idx & 15;
                if (base + row < N) {
                    uint4 v = *(uint4*)(sm + row * 272 + s * 16);
                    int dst = (s < 8) ? 256 + s * 16 : 640 + (s - 8) * 16;
                    *(uint4*)&g_proj[(size_t)(base + row) * 768 + dst] = v;
                }
            }
        }
    }
}

// ---------------------------------------------------------------- stage 2 ---
struct S2 {
    unsigned char ha[TILE_E][144];   // 9216 B, e4m3 hidden
    unsigned char A2s[64][144];      // 9216 B, e4m3 A2^T [n][k]
    float ab2s[64];
    float pen[TILE_E];
    int   maxsend[TILE_E];
    uint  srcOff[TILE_E];            // pre-multiplied byte offsets (node*768)
    uint  tgtOff[TILE_E];
};

__global__ void __launch_bounds__(256, 6)
edge_kernel(const int*   __restrict__ edges,
            const int*   __restrict__ army,
            const float* __restrict__ b1,
            const float* __restrict__ W2,
            const float* __restrict__ b2,
            const float* __restrict__ ab1,
            float* __restrict__ out,
            int E)
{
    extern __shared__ char smem_raw[];
    S2* S = (S2*)smem_raw;
    const int t = threadIdx.x;

    #pragma unroll
    for (int i = 0; i < 2; ++i) {
        int idx = t + 256 * i;
        int col = idx >> 3, chunk = idx & 7;
        uint4 v = *(const uint4*)&g_A2f8[col * 128 + chunk * 16];
        *(uint4*)&S->A2s[col][chunk * 16] = v;
    }
    if (t < 64) S->ab2s[t] = g_ab2[t];

    const int w = t >> 5, l = t & 31;
    const unsigned char* __restrict__ projc = g_proj;

    const int half = l >> 4;
    const int fl   = l & 15;
    const int f8   = fl * 8;

    __half2 b1h[4], ab1h[4], w2h[4];
    {
        float4 xa = ((const float4*)(b1 + f8))[0];
        float4 xb = ((const float4*)(b1 + f8))[1];
        b1h[0] = __floats2half2_rn(xa.x, xa.y); b1h[1] = __floats2half2_rn(xa.z, xa.w);
        b1h[2] = __floats2half2_rn(xb.x, xb.y); b1h[3] = __floats2half2_rn(xb.z, xb.w);
        float4 ya = ((const float4*)(ab1 + f8))[0];
        float4 yb = ((const float4*)(ab1 + f8))[1];
        ab1h[0] = __floats2half2_rn(ya.x, ya.y); ab1h[1] = __floats2half2_rn(ya.z, ya.w);
        ab1h[2] = __floats2half2_rn(yb.x, yb.y); ab1h[3] = __floats2half2_rn(yb.z, yb.w);
        float4 za = ((const float4*)(W2 + f8))[0];
        float4 zb = ((const float4*)(W2 + f8))[1];
        w2h[0] = __floats2half2_rn(za.x, za.y); w2h[1] = __floats2half2_rn(za.z, za.w);
        w2h[2] = __floats2half2_rn(zb.x, zb.y); w2h[3] = __floats2half2_rn(zb.z, zb.w);
    }
    const float b2v = b2[0];
    const __half2 zero2 = __half2half2(__float2half(0.f));

    __syncthreads();

    const int mtile   = w >> 1;
    const int cbase   = (w & 1) * 32;
    const int wbase16 = mtile * 16;
    unsigned haBase = (unsigned)__cvta_generic_to_shared(&S->ha[0][0]);
    unsigned a2Base = (unsigned)__cvta_generic_to_shared(&S->A2s[0][0]);
    const int m = l >> 3;
    const int arow   = wbase16 + (l & 7) + (m & 1) * 8;
    const int abyte  = (m >> 1) * 16;
    const int bcol   = (m & 1) * 8 + (l & 7);
    const int bbyte  = (m >> 1) * 16;
    float ab2r[4][2];
    #pragma unroll
    for (int nt = 0; nt < 4; ++nt) {
        ab2r[nt][0] = S->ab2s[cbase + nt * 8 + 2 * (l & 3)];
        ab2r[nt][1] = S->ab2s[cbase + nt * 8 + 2 * (l & 3) + 1];
    }

    const int wbase8 = w * 8;

    for (int it = 0; it < ITER; ++it) {
        const int blockBase = (blockIdx.x * ITER + it) * TILE_E;

        if (t < TILE_E) {
            int e = blockBase + t;
            int s = 0, g = 0, ms = -1; float pen = 0.f;
            if (e < E) {
                s = __ldcs(&edges[2 * e]); g = __ldcs(&edges[2 * e + 1]);
                int sa = army[s], ta = army[g];
                ms = sa - 1;
                if (sa <= 2 || ta >= 3 * sa) pen += 1.f;
                if (s == g) pen += 100.f;
            }
            S->srcOff[t] = (uint)s * 768u;
            S->tgtOff[t] = (uint)g * 768u;
            S->maxsend[t] = ms; S->pen[t] = pen;
        }
        __syncthreads();

        // Phase 1: 4 iterations x 2 edges/warp (lane halves), double-buffered.
        uint4 wsv[2], wtv[2];
        uint2 pav[2], ptv[2];
        {
            const int le = wbase8 + half;
            const uint sB = S->srcOff[le];
            const uint tB = S->tgtOff[le];
            wsv[0] = *(const uint4*)(projc + sB + f8 * 2);
            pav[0] = *(const uint2*)(projc + sB + 256 + f8);
            wtv[0] = *(const uint4*)(projc + tB + 384 + f8 * 2);
            ptv[0] = *(const uint2*)(projc + tB + 640 + f8);
        }

        #pragma unroll
        for (int i = 0; i < 4; ++i) {
            const int cur = i & 1, nxt = cur ^ 1;
            if (i < 3) {
                const int le = wbase8 + 2 * (i + 1) + half;
                const uint sB = S->srcOff[le];
                const uint tB = S->tgtOff[le];
                wsv[nxt] = *(const uint4*)(projc + sB + f8 * 2);
                pav[nxt] = *(const uint2*)(projc + sB + 256 + f8);
                wtv[nxt] = *(const uint4*)(projc + tB + 384 + f8 * 2);
                ptv[nxt] = *(const uint2*)(projc + tB + 640 + f8);
            }
            const int le = wbase8 + 2 * i + half;
            const int e  = blockBase + le;

            __half2 sw[4], tw[4];
            sw[0] = *(__half2*)&wsv[cur].x; sw[1] = *(__half2*)&wsv[cur].y;
            sw[2] = *(__half2*)&wsv[cur].z; sw[3] = *(__half2*)&wsv[cur].w;
            tw[0] = *(__half2*)&wtv[cur].x; tw[1] = *(__half2*)&wtv[cur].y;
            tw[2] = *(__half2*)&wtv[cur].z; tw[3] = *(__half2*)&wtv[cur].w;
            __half2 acc2 = zero2;
            #pragma unroll
            for (int q = 0; q < 4; ++q) {
                __half2 h = __hmax2(__hadd2(__hadd2(sw[q], tw[q]), b1h[q]), zero2);
                acc2 = __hfma2(h, w2h[q], acc2);
            }
            float2 pf = __half22float2(acc2);
            float part = pf.x + pf.y;
            #pragma unroll
            for (int d = 8; d > 0; d >>= 1)
                part += __shfl_xor_sync(0xffffffffu, part, d);
            if (fl == 0 && e < E) __stcs(&out[e], part + b2v - S->pen[le]);

            uint sa01, sa23, sa45, sa67, ta01, ta23, ta45, ta67;
            unpack_e4m3_4(pav[cur].x, sa01, sa23);
            unpack_e4m3_4(pav[cur].y, sa45, sa67);
            unpack_e4m3_4(ptv[cur].x, ta01, ta23);
            unpack_e4m3_4(ptv[cur].y, ta45, ta67);
            __half2 g0 = __hmax2(__hadd2(__hadd2(*(__half2*)&sa01, *(__half2*)&ta01), ab1h[0]), zero2);
            __half2 g1 = __hmax2(__hadd2(__hadd2(*(__half2*)&sa23, *(__half2*)&ta23), ab1h[1]), zero2);
            __half2 g2 = __hmax2(__hadd2(__hadd2(*(__half2*)&sa45, *(__half2*)&ta45), ab1h[2]), zero2);
            __half2 g3 = __hmax2(__hadd2(__hadd2(*(__half2*)&sa67, *(__half2*)&ta67), ab1h[3]), zero2);
            unsigned short q0 = cvt_f16x2_e4m3x2(*(uint*)&g0);
            unsigned short q1 = cvt_f16x2_e4m3x2(*(uint*)&g1);
            unsigned short q2 = cvt_f16x2_e4m3x2(*(uint*)&g2);
            unsigned short q3 = cvt_f16x2_e4m3x2(*(uint*)&g3);
            uint2 stv;
            asm("mov.b32 %0, {%1, %2};" : "=r"(stv.x) : "h"(q0), "h"(q1));
            asm("mov.b32 %0, {%1, %2};" : "=r"(stv.y) : "h"(q2), "h"(q3));
            *(uint2*)&S->ha[le][f8] = stv;
        }
        __syncthreads();

        // Phase 2: army GEMM, fp8 m16n8k32.
        float c[4][4];
        #pragma unroll
        for (int nt = 0; nt < 4; ++nt) {
            c[nt][0] = ab2r[nt][0]; c[nt][1] = ab2r[nt][1];
            c[nt][2] = ab2r[nt][0]; c[nt][3] = ab2r[nt][1];
        }

        #pragma unroll
        for (int ks = 0; ks < 4; ++ks) {
            const int kb = ks * 32;
            unsigned a0, a1, a2, a3;
            unsigned aaddr = haBase + (unsigned)(arow * 144 + kb + abyte);
            asm volatile("ldmatrix.sync.aligned.m8n8.x4.shared.b16 {%0,%1,%2,%3}, [%4];"
                         : "=r"(a0), "=r"(a1), "=r"(a2), "=r"(a3) : "r"(aaddr));
            #pragma unroll
            for (int g2i = 0; g2i < 2; ++g2i) {
                unsigned b0, b1r, b2r, b3r;
                unsigned baddr = a2Base + (unsigned)((cbase + g2i * 16 + bcol) * 144 + kb + bbyte);
                asm volatile("ldmatrix.sync.aligned.m8n8.x4.shared.b16 {%0,%1,%2,%3}, [%4];"
                             : "=r"(b0), "=r"(b1r), "=r"(b2r), "=r"(b3r) : "r"(baddr));
                asm volatile("mma.sync.aligned.m16n8k32.row.col.f32.e4m3.e4m3.f32 "
                             "{%0,%1,%2,%3},{%4,%5,%6,%7},{%8,%9},{%0,%1,%2,%3};"
                             : "+f"(c[2*g2i][0]), "+f"(c[2*g2i][1]), "+f"(c[2*g2i][2]), "+f"(c[2*g2i][3])
                             : "r"(a0), "r"(a1), "r"(a2), "r"(a3), "r"(b0), "r"(b2r));
                asm volatile("mma.sync.aligned.m16n8k32.row.col.f32.e4m3.e4m3.f32 "
                             "{%0,%1,%2,%3},{%4,%5,%6,%7},{%8,%9},{%0,%1,%2,%3};"
                             : "+f"(c[2*g2i+1][0]), "+f"(c[2*g2i+1][1]), "+f"(c[2*g2i+1][2]), "+f"(c[2*g2i+1][3])
                             : "r"(a0), "r"(a1), "r"(a2), "r"(a3), "r"(b1r), "r"(b3r));
            }
        }

        // Epilogue.
        const int r0 = wbase16 + (l >> 2);
        const int e0 = blockBase + r0;
        const int e1 = e0 + 8;
        const int ms0 = S->maxsend[r0];
        const int ms1 = S->maxsend[r0 + 8];
        #pragma unroll
        for (int nt = 0; nt < 4; ++nt) {
            const int col = cbase + nt * 8 + 2 * (l & 3);
            if (e0 < E) {
                float2 v;
                v.x = (col     <= ms0) ? c[nt][0] : -1.0e9f;
                v.y = (col + 1 <= ms0) ? c[nt][1] : -1.0e9f;
                __stcs((float2*)&out[(size_t)E + (size_t)e0 * 64 + col], v);
            }
            if (e1 < E) {
                float2 v;
                v.x = (col     <= ms1) ? c[nt][2] : -1.0e9f;
                v.y = (col + 1 <= ms1) ? c[nt][3] : -1.0e9f;
                __stcs((float2*)&out[(size_t)E + (size_t)e1 * 64 + col], v);
            }
        }
        __syncthreads();
    }
}

// ---------------------------------------------------------------- launch ----
extern "C" void kernel_launch(void* const* d_in, const int* in_sizes, int n_in,
                              void* d_out, int out_size)
{
    const float* emb   = (const float*)d_in[0];
    const int*   edges = (const int*)  d_in[1];
    const int*   army  = (const int*)  d_in[2];
    const float* W1    = (const float*)d_in[3];
    const float* b1    = (const float*)d_in[4];
    const float* W2    = (const float*)d_in[5];
    const float* b2    = (const float*)d_in[6];
    const float* A1    = (const float*)d_in[7];
    const float* ab1   = (const float*)d_in[8];
    const float* A2    = (const float*)d_in[9];
    const float* ab2   = (const float*)d_in[10];
    float* out = (float*)d_out;

    int N = in_sizes[0] / 128;
    int E = in_sizes[1] / 2;
    if (N > MAX_N) N = MAX_N;

    a2prep_kernel<<<1, 256>>>(A2, ab2);
    wprep_kernel<<<2, 256>>>(W1, A1);

    cudaFuncSetAttribute(precompute_kernel,
                         cudaFuncAttributeMaxDynamicSharedMemorySize, S1_TOTAL);
    precompute_kernel<<<(N + 63) / 64, 256, S1_TOTAL>>>(emb, N);

    cudaFuncSetAttribute(edge_kernel, cudaFuncAttributeMaxDynamicSharedMemorySize,
                         (int)sizeof(S2));
    int eblk = (E + TILE_E * ITER - 1) / (TILE_E * ITER);
    edge_kernel<<<eblk, 256, sizeof(S2)>>>(
        edges, army, b1, W2, b2, ab1, out, E);
}

// round 16
// speedup vs baseline: 1.0907x; 1.0907x over previous
#include <cuda_runtime.h>
#include <cuda_bf16.h>
#include <cuda_fp16.h>
#include <cstdint>

typedef unsigned int uint;

#define MAX_N  100000
#define TILE_E 64
#define ITER   8      // edge tiles per block

// Interleaved per-node table, 768 bytes:
//  [0:256)    W src-half: 128 fp16
//  [256:384)  A src-half: 128 e4m3
//  [384:640)  W tgt-half: 128 fp16
//  [640:768)  A tgt-half: 128 e4m3
static __device__ unsigned char g_proj[(size_t)MAX_N * 768];
static __device__ unsigned char g_A2f8[64 * 128];     // A2^T as [n][k] e4m3
static __device__ float         g_ab2[64];
static __device__ unsigned char g_Wswz[2][256 * 256]; // pre-swizzled fp16 weight images

__device__ __forceinline__ unsigned short pack_e4m3_2(float f0, float f1) {
    unsigned short r;
    asm("cvt.rn.satfinite.e4m3x2.f32 %0, %2, %1;" : "=h"(r) : "f"(f0), "f"(f1));
    return r;
}

__device__ __forceinline__ unsigned short cvt_f16x2_e4m3x2(uint h2) {
    unsigned short r;
    asm("cvt.rn.satfinite.e4m3x2.f16x2 %0, %1;" : "=h"(r) : "r"(h2));
    return r;
}

__device__ __forceinline__ void unpack_e4m3_4(uint v, uint& h01, uint& h23) {
    asm("{\n\t.reg .b16 lo, hi;\n\t"
        "mov.b32 {lo, hi}, %2;\n\t"
        "cvt.rn.f16x2.e4m3x2 %0, lo;\n\t"
        "cvt.rn.f16x2.e4m3x2 %1, hi;\n\t}"
        : "=r"(h01), "=r"(h23) : "r"(v));
}

// ------------------------------------------------------------- prep ---------
__global__ void __launch_bounds__(256)
a2prep_kernel(const float* __restrict__ A2, const float* __restrict__ ab2)
{
    const int t = threadIdx.x;
    const int n = t >> 2, kc = t & 3;
    #pragma unroll
    for (int j = 0; j < 8; ++j) {
        int k = kc * 32 + j * 4;
        float f0 = A2[(size_t)(k + 0) * 64 + n];
        float f1 = A2[(size_t)(k + 1) * 64 + n];
        float f2 = A2[(size_t)(k + 2) * 64 + n];
        float f3 = A2[(size_t)(k + 3) * 64 + n];
        unsigned short lo = pack_e4m3_2(f0, f1);
        unsigned short hi = pack_e4m3_2(f2, f3);
        uint v;
        asm("mov.b32 %0, {%1, %2};" : "=r"(v) : "h"(lo), "h"(hi));
        *(uint*)&g_A2f8[n * 128 + k] = v;
    }
    if (t < 64) g_ab2[t] = ab2[t];
}

__global__ void __launch_bounds__(256)
wprep_kernel(const float* __restrict__ W1, const float* __restrict__ A1)
{
    int c = blockIdx.x * 256 + threadIdx.x;
    int img = c >> 8, col = c & 255;
    const float* __restrict__ Wm = img ? A1 : W1;
    int koff = (col >= 128) ? 128 : 0;
    int cc = col - koff;
    unsigned char* dst = g_Wswz[img] + col * 256;
    #pragma unroll 4
    for (int k = 0; k < 128; k += 2) {
        float f0 = Wm[(size_t)(koff + k)     * 128 + cc];
        float f1 = Wm[(size_t)(koff + k + 1) * 128 + cc];
        __half2 h = __floats2half2_rn(f0, f1);
        int byte = (2 * k) ^ (16 * ((col >> 2) & 7));
        *(uint*)(dst + byte) = *(uint*)&h;
    }
}

// ---------------------------------------------------------------- stage 1 ---
#define S1_WS     0
#define S1_AS     69632
#define S1_TOTAL  87040

__global__ void __launch_bounds__(256, 2)
precompute_kernel(const float* __restrict__ emb, int N)
{
    extern __shared__ char sm[];
    char* Ws = sm + S1_WS;
    char* As = sm + S1_AS;

    const int t    = threadIdx.x;
    const int base = blockIdx.x * 64;

    #pragma unroll
    for (int j = 0; j < 8; ++j) {
        int idx = t + 256 * j;
        int row = idx >> 5, q = idx & 31;
        int n = base + row; if (n >= N) n = N - 1;
        float4 v = ((const float4*)emb)[(size_t)n * 32 + q];
        __half2 h0 = __floats2half2_rn(v.x, v.y);
        __half2 h1 = __floats2half2_rn(v.z, v.w);
        uint2 st; st.x = *(uint*)&h0; st.y = *(uint*)&h1;
        *(uint2*)(As + row * 272 + q * 8) = st;
    }

    const int w = t >> 5, l = t & 31;
    const int wm = w >> 2, wn = w & 3;
    const int rbase = wm * 32;
    const int cbase = wn * 64;
    const int lq = l >> 2, lr = l & 3;
    const int m  = l >> 3;

    unsigned wsBase = (unsigned)__cvta_generic_to_shared(Ws);
    unsigned asBase = (unsigned)__cvta_generic_to_shared(As);

    const int arow_off = (m & 1) * 8 + (l & 7);
    const int aksel    = (m >> 1) * 16;
    const int brow_off = (m >> 1) * 8 + (l & 7);
    const int bksel    = (m & 1) * 16;

    #pragma unroll 1
    for (int img = 0; img < 2; ++img) {
        __syncthreads();
        {
            const unsigned char* src = g_Wswz[img];
            #pragma unroll
            for (int j = 0; j < 16; ++j) {
                int idx = t + 256 * j;
                int col = idx >> 4, chunk = idx & 15;
                uint4 v = *(const uint4*)(src + col * 256 + chunk * 16);
                *(uint4*)(Ws + col * 272 + chunk * 16) = v;
            }
        }
        __syncthreads();

        float c[2][8][4];
        #pragma unroll
        for (int mt = 0; mt < 2; ++mt)
            #pragma unroll
            for (int nt = 0; nt < 8; ++nt)
                #pragma unroll
                for (int i = 0; i < 4; ++i) c[mt][nt][i] = 0.f;

        #pragma unroll
        for (int ks = 0; ks < 8; ++ks) {
            uint a[2][4];
            #pragma unroll
            for (int mt = 0; mt < 2; ++mt) {
                int row = rbase + mt * 16 + arow_off;
                unsigned addr = asBase + (unsigned)(row * 272 + ks * 32 + aksel);
                asm volatile("ldmatrix.sync.aligned.m8n8.x4.shared.b16 {%0,%1,%2,%3}, [%4];"
                             : "=r"(a[mt][0]), "=r"(a[mt][1]), "=r"(a[mt][2]), "=r"(a[mt][3])
                             : "r"(addr));
            }
            #pragma unroll
            for (int nt2 = 0; nt2 < 4; ++nt2) {
                int row = cbase + nt2 * 16 + brow_off;
                int byte = (ks * 32 + bksel) ^ (16 * ((row >> 2) & 7));
                unsigned addr = wsBase + (unsigned)(row * 272 + byte);
                uint b0, b1, b2, b3;
                asm volatile("ldmatrix.sync.aligned.m8n8.x4.shared.b16 {%0,%1,%2,%3}, [%4];"
                             : "=r"(b0), "=r"(b1), "=r"(b2), "=r"(b3) : "r"(addr));
                #pragma unroll
                for (int mt = 0; mt < 2; ++mt) {
                    asm volatile("mma.sync.aligned.m16n8k16.row.col.f32.f16.f16.f32 "
                                 "{%0,%1,%2,%3},{%4,%5,%6,%7},{%8,%9},{%0,%1,%2,%3};"
                                 : "+f"(c[mt][2*nt2][0]), "+f"(c[mt][2*nt2][1]),
                                   "+f"(c[mt][2*nt2][2]), "+f"(c[mt][2*nt2][3])
                                 : "r"(a[mt][0]), "r"(a[mt][1]), "r"(a[mt][2]), "r"(a[mt][3]),
                                   "r"(b0), "r"(b1));
                    asm volatile("mma.sync.aligned.m16n8k16.row.col.f32.f16.f16.f32 "
                                 "{%0,%1,%2,%3},{%4,%5,%6,%7},{%8,%9},{%0,%1,%2,%3};"
                                 : "+f"(c[mt][2*nt2+1][0]), "+f"(c[mt][2*nt2+1][1]),
                                   "+f"(c[mt][2*nt2+1][2]), "+f"(c[mt][2*nt2+1][3])
                                 : "r"(a[mt][0]), "r"(a[mt][1]), "r"(a[mt][2]), "r"(a[mt][3]),
                                   "r"(b2), "r"(b3));
                }
            }
        }
        __syncthreads();

        if (img == 0) {
            #pragma unroll
            for (int mt = 0; mt < 2; ++mt) {
                #pragma unroll
                for (int nt = 0; nt < 8; ++nt) {
                    int r  = rbase + mt * 16 + lq;
                    int cc = cbase + nt * 8 + 2 * lr;
                    __half2 h01 = __floats2half2_rn(c[mt][nt][0], c[mt][nt][1]);
                    __half2 h23 = __floats2half2_rn(c[mt][nt][2], c[mt][nt][3]);
                    *(uint*)(sm + r * 528 + cc * 2)       = *(uint*)&h01;
                    *(uint*)(sm + (r + 8) * 528 + cc * 2) = *(uint*)&h23;
                }
            }
            __syncthreads();
            #pragma unroll
            for (int j = 0; j < 8; ++j) {
                int idx = t + 256 * j;
                int row = idx >> 5, s = idx & 31;
                if (base + row < N) {
                    uint4 v = *(uint4*)(sm + row * 528 + s * 16);
                    int dst = (s < 16) ? s * 16 : 384 + (s - 16) * 16;
                    *(uint4*)&g_proj[(size_t)(base + row) * 768 + dst] = v;
                }
            }
        } else {
            #pragma unroll
            for (int mt = 0; mt < 2; ++mt) {
                #pragma unroll
                for (int nt = 0; nt < 8; ++nt) {
                    int r  = rbase + mt * 16 + lq;
                    int cc = cbase + nt * 8 + 2 * lr;
                    *(unsigned short*)(sm + r * 272 + cc)       = pack_e4m3_2(c[mt][nt][0], c[mt][nt][1]);
                    *(unsigned short*)(sm + (r + 8) * 272 + cc) = pack_e4m3_2(c[mt][nt][2], c[mt][nt][3]);
                }
            }
            __syncthreads();
            #pragma unroll
            for (int j = 0; j < 4; ++j) {
                int idx = t + 256 * j;
                int row = idx >> 4, s = idx & 15;
                if (base + row < N) {
                    uint4 v = *(uint4*)(sm + row * 272 + s * 16);
                    int dst = (s < 8) ? 256 + s * 16 : 640 + (s - 8) * 16;
                    *(uint4*)&g_proj[(size_t)(base + row) * 768 + dst] = v;
                }
            }
        }
    }
}

// ---------------------------------------------------------------- stage 2 ---
struct S2 {
    unsigned char ha[TILE_E][144];   // 9216 B, e4m3 hidden
    unsigned char A2s[64][144];      // 9216 B, e4m3 A2^T [n][k]
    float ab2s[64];
    float pen[TILE_E];
    int   maxsend[TILE_E];
    uint  srcOff[TILE_E];            // pre-multiplied byte offsets (node*768)
    uint  tgtOff[TILE_E];
};

__global__ void __launch_bounds__(256, 5)
edge_kernel(const int*   __restrict__ edges,
            const int*   __restrict__ army,
            const float* __restrict__ b1,
            const float* __restrict__ W2,
            const float* __restrict__ b2,
            const float* __restrict__ ab1,
            float* __restrict__ out,
            int E)
{
    extern __shared__ char smem_raw[];
    S2* S = (S2*)smem_raw;
    const int t = threadIdx.x;

    #pragma unroll
    for (int i = 0; i < 2; ++i) {
        int idx = t + 256 * i;
        int col = idx >> 3, chunk = idx & 7;
        uint4 v = *(const uint4*)&g_A2f8[col * 128 + chunk * 16];
        *(uint4*)&S->A2s[col][chunk * 16] = v;
    }
    if (t < 64) S->ab2s[t] = g_ab2[t];

    const int w = t >> 5, l = t & 31;
    const unsigned char* __restrict__ projc = g_proj;

    const int half = l >> 4;
    const int fl   = l & 15;
    const int f8   = fl * 8;

    __half2 b1h[4], ab1h[4], w2h[4];
    {
        float4 xa = ((const float4*)(b1 + f8))[0];
        float4 xb = ((const float4*)(b1 + f8))[1];
        b1h[0] = __floats2half2_rn(xa.x, xa.y); b1h[1] = __floats2half2_rn(xa.z, xa.w);
        b1h[2] = __floats2half2_rn(xb.x, xb.y); b1h[3] = __floats2half2_rn(xb.z, xb.w);
        float4 ya = ((const float4*)(ab1 + f8))[0];
        float4 yb = ((const float4*)(ab1 + f8))[1];
        ab1h[0] = __floats2half2_rn(ya.x, ya.y); ab1h[1] = __floats2half2_rn(ya.z, ya.w);
        ab1h[2] = __floats2half2_rn(yb.x, yb.y); ab1h[3] = __floats2half2_rn(yb.z, yb.w);
        float4 za = ((const float4*)(W2 + f8))[0];
        float4 zb = ((const float4*)(W2 + f8))[1];
        w2h[0] = __floats2half2_rn(za.x, za.y); w2h[1] = __floats2half2_rn(za.z, za.w);
        w2h[2] = __floats2half2_rn(zb.x, zb.y); w2h[3] = __floats2half2_rn(zb.z, zb.w);
    }
    const float b2v = b2[0];
    const __half2 zero2 = __half2half2(__float2half(0.f));

    __syncthreads();

    const int mtile   = w >> 1;
    const int cbase   = (w & 1) * 32;
    const int wbase16 = mtile * 16;
    unsigned haBase = (unsigned)__cvta_generic_to_shared(&S->ha[0][0]);
    unsigned a2Base = (unsigned)__cvta_generic_to_shared(&S->A2s[0][0]);
    const int m = l >> 3;
    const int arow   = wbase16 + (l & 7) + (m & 1) * 8;
    const int abyte  = (m >> 1) * 16;
    const int bcol   = (m & 1) * 8 + (l & 7);
    const int bbyte  = (m >> 1) * 16;
    float ab2r[4][2];
    #pragma unroll
    for (int nt = 0; nt < 4; ++nt) {
        ab2r[nt][0] = S->ab2s[cbase + nt * 8 + 2 * (l & 3)];
        ab2r[nt][1] = S->ab2s[cbase + nt * 8 + 2 * (l & 3) + 1];
    }

    const int wbase8 = w * 8;

    for (int it = 0; it < ITER; ++it) {
        const int blockBase = (blockIdx.x * ITER + it) * TILE_E;

        if (t < TILE_E) {
            int e = blockBase + t;
            int s = 0, g = 0, ms = -1; float pen = 0.f;
            if (e < E) {
                s = __ldcs(&edges[2 * e]); g = __ldcs(&edges[2 * e + 1]);
                int sa = army[s], ta = army[g];
                ms = sa - 1;
                if (sa <= 2 || ta >= 3 * sa) pen += 1.f;
                if (s == g) pen += 100.f;
            }
            S->srcOff[t] = (uint)s * 768u;
            S->tgtOff[t] = (uint)g * 768u;
            S->maxsend[t] = ms; S->pen[t] = pen;
        }
        __syncthreads();

        // Phase 1: 4 iterations x 2 edges/warp (lane halves), double-buffered.
        uint4 wsv[2], wtv[2];
        uint2 pav[2], ptv[2];
        {
            const int le = wbase8 + half;
            const uint sB = S->srcOff[le];
            const uint tB = S->tgtOff[le];
            wsv[0] = *(const uint4*)(projc + sB + f8 * 2);
            pav[0] = *(const uint2*)(projc + sB + 256 + f8);
            wtv[0] = *(const uint4*)(projc + tB + 384 + f8 * 2);
            ptv[0] = *(const uint2*)(projc + tB + 640 + f8);
        }

        #pragma unroll
        for (int i = 0; i < 4; ++i) {
            const int cur = i & 1, nxt = cur ^ 1;
            if (i < 3) {
                const int le = wbase8 + 2 * (i + 1) + half;
                const uint sB = S->srcOff[le];
                const uint tB = S->tgtOff[le];
                wsv[nxt] = *(const uint4*)(projc + sB + f8 * 2);
                pav[nxt] = *(const uint2*)(projc + sB + 256 + f8);
                wtv[nxt] = *(const uint4*)(projc + tB + 384 + f8 * 2);
                ptv[nxt] = *(const uint2*)(projc + tB + 640 + f8);
            }
            const int le = wbase8 + 2 * i + half;
            const int e  = blockBase + le;

            __half2 sw[4], tw[4];
            sw[0] = *(__half2*)&wsv[cur].x; sw[1] = *(__half2*)&wsv[cur].y;
            sw[2] = *(__half2*)&wsv[cur].z; sw[3] = *(__half2*)&wsv[cur].w;
            tw[0] = *(__half2*)&wtv[cur].x; tw[1] = *(__half2*)&wtv[cur].y;
            tw[2] = *(__half2*)&wtv[cur].z; tw[3] = *(__half2*)&wtv[cur].w;
            __half2 acc2 = zero2;
            #pragma unroll
            for (int q = 0; q < 4; ++q) {
                __half2 h = __hmax2(__hadd2(__hadd2(sw[q], tw[q]), b1h[q]), zero2);
                acc2 = __hfma2(h, w2h[q], acc2);
            }
            float2 pf = __half22float2(acc2);
            float part = pf.x + pf.y;
            #pragma unroll
            for (int d = 8; d > 0; d >>= 1)
                part += __shfl_xor_sync(0xffffffffu, part, d);
            if (fl == 0 && e < E) __stcs(&out[e], part + b2v - S->pen[le]);

            uint sa01, sa23, sa45, sa67, ta01, ta23, ta45, ta67;
            unpack_e4m3_4(pav[cur].x, sa01, sa23);
            unpack_e4m3_4(pav[cur].y, sa45, sa67);
            unpack_e4m3_4(ptv[cur].x, ta01, ta23);
            unpack_e4m3_4(ptv[cur].y, ta45, ta67);
            __half2 g0 = __hmax2(__hadd2(__hadd2(*(__half2*)&sa01, *(__half2*)&ta01), ab1h[0]), zero2);
            __half2 g1 = __hmax2(__hadd2(__hadd2(*(__half2*)&sa23, *(__half2*)&ta23), ab1h[1]), zero2);
            __half2 g2 = __hmax2(__hadd2(__hadd2(*(__half2*)&sa45, *(__half2*)&ta45), ab1h[2]), zero2);
            __half2 g3 = __hmax2(__hadd2(__hadd2(*(__half2*)&sa67, *(__half2*)&ta67), ab1h[3]), zero2);
            unsigned short q0 = cvt_f16x2_e4m3x2(*(uint*)&g0);
            unsigned short q1 = cvt_f16x2_e4m3x2(*(uint*)&g1);
            unsigned short q2 = cvt_f16x2_e4m3x2(*(uint*)&g2);
            unsigned short q3 = cvt_f16x2_e4m3x2(*(uint*)&g3);
            uint2 stv;
            asm("mov.b32 %0, {%1, %2};" : "=r"(stv.x) : "h"(q0), "h"(q1));
            asm("mov.b32 %0, {%1, %2};" : "=r"(stv.y) : "h"(q2), "h"(q3));
            *(uint2*)&S->ha[le][f8] = stv;
        }
        __syncthreads();

        // Phase 2: army GEMM, fp8 m16n8k32.
        float c[4][4];
        #pragma unroll
        for (int nt = 0; nt < 4; ++nt) {
            c[nt][0] = ab2r[nt][0]; c[nt][1] = ab2r[nt][1];
            c[nt][2] = ab2r[nt][0]; c[nt][3] = ab2r[nt][1];
        }

        #pragma unroll
        for (int ks = 0; ks < 4; ++ks) {
            const int kb = ks * 32;
            unsigned a0, a1, a2, a3;
            unsigned aaddr = haBase + (unsigned)(arow * 144 + kb + abyte);
            asm volatile("ldmatrix.sync.aligned.m8n8.x4.shared.b16 {%0,%1,%2,%3}, [%4];"
                         : "=r"(a0), "=r"(a1), "=r"(a2), "=r"(a3) : "r"(aaddr));
            #pragma unroll
            for (int g2i = 0; g2i < 2; ++g2i) {
                unsigned b0, b1r, b2r, b3r;
                unsigned baddr = a2Base + (unsigned)((cbase + g2i * 16 + bcol) * 144 + kb + bbyte);
                asm volatile("ldmatrix.sync.aligned.m8n8.x4.shared.b16 {%0,%1,%2,%3}, [%4];"
                             : "=r"(b0), "=r"(b1r), "=r"(b2r), "=r"(b3r) : "r"(baddr));
                asm volatile("mma.sync.aligned.m16n8k32.row.col.f32.e4m3.e4m3.f32 "
                             "{%0,%1,%2,%3},{%4,%5,%6,%7},{%8,%9},{%0,%1,%2,%3};"
                             : "+f"(c[2*g2i][0]), "+f"(c[2*g2i][1]), "+f"(c[2*g2i][2]), "+f"(c[2*g2i][3])
                             : "r"(a0), "r"(a1), "r"(a2), "r"(a3), "r"(b0), "r"(b2r));
                asm volatile("mma.sync.aligned.m16n8k32.row.col.f32.e4m3.e4m3.f32 "
                             "{%0,%1,%2,%3},{%4,%5,%6,%7},{%8,%9},{%0,%1,%2,%3};"
                             : "+f"(c[2*g2i+1][0]), "+f"(c[2*g2i+1][1]), "+f"(c[2*g2i+1][2]), "+f"(c[2*g2i+1][3])
                             : "r"(a0), "r"(a1), "r"(a2), "r"(a3), "r"(b1r), "r"(b3r));
            }
        }

        // Epilogue.
        const int r0 = wbase16 + (l >> 2);
        const int e0 = blockBase + r0;
        const int e1 = e0 + 8;
        const int ms0 = S->maxsend[r0];
        const int ms1 = S->maxsend[r0 + 8];
        #pragma unroll
        for (int nt = 0; nt < 4; ++nt) {
            const int col = cbase + nt * 8 + 2 * (l & 3);
            if (e0 < E) {
                float2 v;
                v.x = (col     <= ms0) ? c[nt][0] : -1.0e9f;
                v.y = (col + 1 <= ms0) ? c[nt][1] : -1.0e9f;
                __stcs((float2*)&out[(size_t)E + (size_t)e0 * 64 + col], v);
            }
            if (e1 < E) {
                float2 v;
                v.x = (col     <= ms1) ? c[nt][2] : -1.0e9f;
                v.y = (col + 1 <= ms1) ? c[nt][3] : -1.0e9f;
                __stcs((float2*)&out[(size_t)E + (size_t)e1 * 64 + col], v);
            }
        }
        __syncthreads();
    }
}

// ---------------------------------------------------------------- launch ----
extern "C" void kernel_launch(void* const* d_in, const int* in_sizes, int n_in,
                              void* d_out, int out_size)
{
    const float* emb   = (const float*)d_in[0];
    const int*   edges = (const int*)  d_in[1];
    const int*   army  = (const int*)  d_in[2];
    const float* W1    = (const float*)d_in[3];
    const float* b1    = (const float*)d_in[4];
    const float* W2    = (const float*)d_in[5];
    const float* b2    = (const float*)d_in[6];
    const float* A1    = (const float*)d_in[7];
    const float* ab1   = (const float*)d_in[8];
    const float* A2    = (const float*)d_in[9];
    const float* ab2   = (const float*)d_in[10];
    float* out = (float*)d_out;

    int N = in_sizes[0] / 128;
    int E = in_sizes[1] / 2;
    if (N > MAX_N) N = MAX_N;

    a2prep_kernel<<<1, 256>>>(A2, ab2);
    wprep_kernel<<<2, 256>>>(W1, A1);

    cudaFuncSetAttribute(precompute_kernel,
                         cudaFuncAttributeMaxDynamicSharedMemorySize, S1_TOTAL);
    precompute_kernel<<<(N + 63) / 64, 256, S1_TOTAL>>>(emb, N);

    cudaFuncSetAttribute(edge_kernel, cudaFuncAttributeMaxDynamicSharedMemorySize,
                         (int)sizeof(S2));
    int eblk = (E + TILE_E * ITER - 1) / (TILE_E * ITER);
    edge_kernel<<<eblk, 256, sizeof(S2)>>>(
        edges, army, b1, W2, b2, ab1, out, E);
}

// round 17
// speedup vs baseline: 1.1878x; 1.0891x over previous
#include <cuda_runtime.h>
#include <cuda_bf16.h>
#include <cuda_fp16.h>
#include <cstdint>

typedef unsigned int uint;

#define MAX_N  100000
#define TILE_E 64
#define ITER   8      // edge tiles per block

// Interleaved per-node table, 768 bytes:
//  [0:256)    W src-half: 128 fp16
//  [256:384)  A src-half: 128 e4m3
//  [384:640)  W tgt-half: 128 fp16
//  [640:768)  A tgt-half: 128 e4m3
static __device__ unsigned char g_proj[(size_t)MAX_N * 768];
static __device__ unsigned char g_A2f8[64 * 128];     // A2^T as [n][k] e4m3
static __device__ float         g_ab2[64];
static __device__ unsigned char g_Wswz[2][256 * 256]; // pre-swizzled fp16 weight images

__device__ __forceinline__ unsigned short pack_e4m3_2(float f0, float f1) {
    unsigned short r;
    asm("cvt.rn.satfinite.e4m3x2.f32 %0, %2, %1;" : "=h"(r) : "f"(f0), "f"(f1));
    return r;
}

__device__ __forceinline__ unsigned short cvt_f16x2_e4m3x2(uint h2) {
    unsigned short r;
    asm("cvt.rn.satfinite.e4m3x2.f16x2 %0, %1;" : "=h"(r) : "r"(h2));
    return r;
}

__device__ __forceinline__ void unpack_e4m3_4(uint v, uint& h01, uint& h23) {
    asm("{\n\t.reg .b16 lo, hi;\n\t"
        "mov.b32 {lo, hi}, %2;\n\t"
        "cvt.rn.f16x2.e4m3x2 %0, lo;\n\t"
        "cvt.rn.f16x2.e4m3x2 %1, hi;\n\t}"
        : "=r"(h01), "=r"(h23) : "r"(v));
}

// ------------------------------------------------------------- prep ---------
__global__ void __launch_bounds__(256)
a2prep_kernel(const float* __restrict__ A2, const float* __restrict__ ab2)
{
    const int t = threadIdx.x;
    const int n = t >> 2, kc = t & 3;
    #pragma unroll
    for (int j = 0; j < 8; ++j) {
        int k = kc * 32 + j * 4;
        float f0 = A2[(size_t)(k + 0) * 64 + n];
        float f1 = A2[(size_t)(k + 1) * 64 + n];
        float f2 = A2[(size_t)(k + 2) * 64 + n];
        float f3 = A2[(size_t)(k + 3) * 64 + n];
        unsigned short lo = pack_e4m3_2(f0, f1);
        unsigned short hi = pack_e4m3_2(f2, f3);
        uint v;
        asm("mov.b32 %0, {%1, %2};" : "=r"(v) : "h"(lo), "h"(hi));
        *(uint*)&g_A2f8[n * 128 + k] = v;
    }
    if (t < 64) g_ab2[t] = ab2[t];
}

__global__ void __launch_bounds__(256)
wprep_kernel(const float* __restrict__ W1, const float* __restrict__ A1)
{
    int c = blockIdx.x * 256 + threadIdx.x;
    int img = c >> 8, col = c & 255;
    const float* __restrict__ Wm = img ? A1 : W1;
    int koff = (col >= 128) ? 128 : 0;
    int cc = col - koff;
    unsigned char* dst = g_Wswz[img] + col * 256;
    #pragma unroll 4
    for (int k = 0; k < 128; k += 2) {
        float f0 = Wm[(size_t)(koff + k)     * 128 + cc];
        float f1 = Wm[(size_t)(koff + k + 1) * 128 + cc];
        __half2 h = __floats2half2_rn(f0, f1);
        int byte = (2 * k) ^ (16 * ((col >> 2) & 7));
        *(uint*)(dst + byte) = *(uint*)&h;
    }
}

// ---------------------------------------------------------------- stage 1 ---
// Persistent: grid ~2/SM. Per block: load Ws image ONCE, loop node tiles.
// C staging reuses the (dead-after-MMA) As region.
#define S1_WS     0        // 256 cols x 272 B = 69632
#define S1_AS     69632    // 64 rows x 272 B = 17408 (also C staging buffer)
#define S1_TOTAL  87040

__global__ void __launch_bounds__(256, 2)
precompute_kernel(const float* __restrict__ emb, int N, int nTiles)
{
    extern __shared__ char sm[];
    char* Ws = sm + S1_WS;
    char* As = sm + S1_AS;

    const int t = threadIdx.x;
    const int w = t >> 5, l = t & 31;
    const int wm = w >> 2, wn = w & 3;
    const int rbase = wm * 32;
    const int cbase = wn * 64;
    const int lq = l >> 2, lr = l & 3;
    const int m  = l >> 3;

    unsigned wsBase = (unsigned)__cvta_generic_to_shared(Ws);
    unsigned asBase = (unsigned)__cvta_generic_to_shared(As);

    const int arow_off = (m & 1) * 8 + (l & 7);
    const int aksel    = (m >> 1) * 16;
    const int brow_off = (m >> 1) * 8 + (l & 7);
    const int bksel    = (m & 1) * 16;

    #pragma unroll 1
    for (int img = 0; img < 2; ++img) {
        __syncthreads();   // prior MMA reads of Ws finished
        {
            const unsigned char* src = g_Wswz[img];
            #pragma unroll
            for (int j = 0; j < 16; ++j) {
                int idx = t + 256 * j;
                int col = idx >> 4, chunk = idx & 15;
                uint4 v = *(const uint4*)(src + col * 256 + chunk * 16);
                *(uint4*)(Ws + col * 272 + chunk * 16) = v;
            }
        }
        __syncthreads();

        #pragma unroll 1
        for (int tile = blockIdx.x; tile < nTiles; tile += gridDim.x) {
            const int base = tile * 64;

            // Load As (64 nodes x 128 k, fp32 -> fp16).
            #pragma unroll
            for (int j = 0; j < 8; ++j) {
                int idx = t + 256 * j;
                int row = idx >> 5, q = idx & 31;
                int n = base + row; if (n >= N) n = N - 1;
                float4 v = ((const float4*)emb)[(size_t)n * 32 + q];
                __half2 h0 = __floats2half2_rn(v.x, v.y);
                __half2 h1 = __floats2half2_rn(v.z, v.w);
                uint2 st; st.x = *(uint*)&h0; st.y = *(uint*)&h1;
                *(uint2*)(As + row * 272 + q * 8) = st;
            }
            __syncthreads();

            float c[2][8][4];
            #pragma unroll
            for (int mt = 0; mt < 2; ++mt)
                #pragma unroll
                for (int nt = 0; nt < 8; ++nt)
                    #pragma unroll
                    for (int i = 0; i < 4; ++i) c[mt][nt][i] = 0.f;

            #pragma unroll
            for (int ks = 0; ks < 8; ++ks) {
                uint a[2][4];
                #pragma unroll
                for (int mt = 0; mt < 2; ++mt) {
                    int row = rbase + mt * 16 + arow_off;
                    unsigned addr = asBase + (unsigned)(row * 272 + ks * 32 + aksel);
                    asm volatile("ldmatrix.sync.aligned.m8n8.x4.shared.b16 {%0,%1,%2,%3}, [%4];"
                                 : "=r"(a[mt][0]), "=r"(a[mt][1]), "=r"(a[mt][2]), "=r"(a[mt][3])
                                 : "r"(addr));
                }
                #pragma unroll
                for (int nt2 = 0; nt2 < 4; ++nt2) {
                    int row = cbase + nt2 * 16 + brow_off;
                    int byte = (ks * 32 + bksel) ^ (16 * ((row >> 2) & 7));
                    unsigned addr = wsBase + (unsigned)(row * 272 + byte);
                    uint b0, b1, b2, b3;
                    asm volatile("ldmatrix.sync.aligned.m8n8.x4.shared.b16 {%0,%1,%2,%3}, [%4];"
                                 : "=r"(b0), "=r"(b1), "=r"(b2), "=r"(b3) : "r"(addr));
                    #pragma unroll
                    for (int mt = 0; mt < 2; ++mt) {
                        asm volatile("mma.sync.aligned.m16n8k16.row.col.f32.f16.f16.f32 "
                                     "{%0,%1,%2,%3},{%4,%5,%6,%7},{%8,%9},{%0,%1,%2,%3};"
                                     : "+f"(c[mt][2*nt2][0]), "+f"(c[mt][2*nt2][1]),
                                       "+f"(c[mt][2*nt2][2]), "+f"(c[mt][2*nt2][3])
                                     : "r"(a[mt][0]), "r"(a[mt][1]), "r"(a[mt][2]), "r"(a[mt][3]),
                                       "r"(b0), "r"(b1));
                        asm volatile("mma.sync.aligned.m16n8k16.row.col.f32.f16.f16.f32 "
                                     "{%0,%1,%2,%3},{%4,%5,%6,%7},{%8,%9},{%0,%1,%2,%3};"
                                     : "+f"(c[mt][2*nt2+1][0]), "+f"(c[mt][2*nt2+1][1]),
                                       "+f"(c[mt][2*nt2+1][2]), "+f"(c[mt][2*nt2+1][3])
                                     : "r"(a[mt][0]), "r"(a[mt][1]), "r"(a[mt][2]), "r"(a[mt][3]),
                                       "r"(b2), "r"(b3));
                    }
                }
            }
            __syncthreads();   // done reading As; reuse As region for C staging

            if (img == 0) {
                // fp16: two 32-row half-passes through the As region (stride 528).
                #pragma unroll 1
                for (int hp = 0; hp < 2; ++hp) {
                    if (wm == hp) {
                        #pragma unroll
                        for (int mt = 0; mt < 2; ++mt) {
                            #pragma unroll
                            for (int nt = 0; nt < 8; ++nt) {
                                int lrow = mt * 16 + lq;         // 0..31 local
                                int cc = cbase + nt * 8 + 2 * lr;
                                __half2 h01 = __floats2half2_rn(c[mt][nt][0], c[mt][nt][1]);
                                __half2 h23 = __floats2half2_rn(c[mt][nt][2], c[mt][nt][3]);
                                *(uint*)(As + lrow * 528 + cc * 2)       = *(uint*)&h01;
                                *(uint*)(As + (lrow + 8) * 528 + cc * 2) = *(uint*)&h23;
                            }
                        }
                    }
                    __syncthreads();
                    #pragma unroll
                    for (int j = 0; j < 4; ++j) {
                        int idx = t + 256 * j;              // 0..1023
                        int row = idx >> 5, s = idx & 31;   // row 0..31 local
                        int grow = hp * 32 + row;
                        if (base + grow < N) {
                            uint4 v = *(uint4*)(As + row * 528 + s * 16);
                            int dst = (s < 16) ? s * 16 : 384 + (s - 16) * 16;
                            *(uint4*)&g_proj[(size_t)(base + grow) * 768 + dst] = v;
                        }
                    }
                    __syncthreads();
                }
            } else {
                // e4m3: all 64 rows (stride 272 = exactly the As region).
                #pragma unroll
                for (int mt = 0; mt < 2; ++mt) {
                    #pragma unroll
                    for (int nt = 0; nt < 8; ++nt) {
                        int r  = rbase + mt * 16 + lq;
                        int cc = cbase + nt * 8 + 2 * lr;
                        *(unsigned short*)(As + r * 272 + cc)       = pack_e4m3_2(c[mt][nt][0], c[mt][nt][1]);
                        *(unsigned short*)(As + (r + 8) * 272 + cc) = pack_e4m3_2(c[mt][nt][2], c[mt][nt][3]);
                    }
                }
                __syncthreads();
                #pragma unroll
                for (int j = 0; j < 4; ++j) {
                    int idx = t + 256 * j;              // 0..1023
                    int row = idx >> 4, s = idx & 15;   // row 0..63
                    if (base + row < N) {
                        uint4 v = *(uint4*)(As + row * 272 + s * 16);
                        int dst = (s < 8) ? 256 + s * 16 : 640 + (s - 8) * 16;
                        *(uint4*)&g_proj[(size_t)(base + row) * 768 + dst] = v;
                    }
                }
                __syncthreads();
            }
        }
    }
}

// ---------------------------------------------------------------- stage 2 ---
struct S2 {
    unsigned char ha[TILE_E][144];   // 9216 B, e4m3 hidden
    unsigned char A2s[64][144];      // 9216 B, e4m3 A2^T [n][k]
    float ab2s[64];
    float pen[TILE_E];
    int   maxsend[TILE_E];
    uint  srcOff[TILE_E];            // pre-multiplied byte offsets (node*768)
    uint  tgtOff[TILE_E];
};

__global__ void __launch_bounds__(256, 5)
edge_kernel(const int*   __restrict__ edges,
            const int*   __restrict__ army,
            const float* __restrict__ b1,
            const float* __restrict__ W2,
            const float* __restrict__ b2,
            const float* __restrict__ ab1,
            float* __restrict__ out,
            int E)
{
    extern __shared__ char smem_raw[];
    S2* S = (S2*)smem_raw;
    const int t = threadIdx.x;

    #pragma unroll
    for (int i = 0; i < 2; ++i) {
        int idx = t + 256 * i;
        int col = idx >> 3, chunk = idx & 7;
        uint4 v = *(const uint4*)&g_A2f8[col * 128 + chunk * 16];
        *(uint4*)&S->A2s[col][chunk * 16] = v;
    }
    if (t < 64) S->ab2s[t] = g_ab2[t];

    const int w = t >> 5, l = t & 31;
    const unsigned char* __restrict__ projc = g_proj;

    const int half = l >> 4;
    const int fl   = l & 15;
    const int f8   = fl * 8;

    __half2 b1h[4], ab1h[4], w2h[4];
    {
        float4 xa = ((const float4*)(b1 + f8))[0];
        float4 xb = ((const float4*)(b1 + f8))[1];
        b1h[0] = __floats2half2_rn(xa.x, xa.y); b1h[1] = __floats2half2_rn(xa.z, xa.w);
        b1h[2] = __floats2half2_rn(xb.x, xb.y); b1h[3] = __floats2half2_rn(xb.z, xb.w);
        float4 ya = ((const float4*)(ab1 + f8))[0];
        float4 yb = ((const float4*)(ab1 + f8))[1];
        ab1h[0] = __floats2half2_rn(ya.x, ya.y); ab1h[1] = __floats2half2_rn(ya.z, ya.w);
        ab1h[2] = __floats2half2_rn(yb.x, yb.y); ab1h[3] = __floats2half2_rn(yb.z, yb.w);
        float4 za = ((const float4*)(W2 + f8))[0];
        float4 zb = ((const float4*)(W2 + f8))[1];
        w2h[0] = __floats2half2_rn(za.x, za.y); w2h[1] = __floats2half2_rn(za.z, za.w);
        w2h[2] = __floats2half2_rn(zb.x, zb.y); w2h[3] = __floats2half2_rn(zb.z, zb.w);
    }
    const float b2v = b2[0];
    const __half2 zero2 = __half2half2(__float2half(0.f));

    __syncthreads();

    const int mtile   = w >> 1;
    const int cbase   = (w & 1) * 32;
    const int wbase16 = mtile * 16;
    unsigned haBase = (unsigned)__cvta_generic_to_shared(&S->ha[0][0]);
    unsigned a2Base = (unsigned)__cvta_generic_to_shared(&S->A2s[0][0]);
    const int m = l >> 3;
    const int arow   = wbase16 + (l & 7) + (m & 1) * 8;
    const int abyte  = (m >> 1) * 16;
    const int bcol   = (m & 1) * 8 + (l & 7);
    const int bbyte  = (m >> 1) * 16;
    float ab2r[4][2];
    #pragma unroll
    for (int nt = 0; nt < 4; ++nt) {
        ab2r[nt][0] = S->ab2s[cbase + nt * 8 + 2 * (l & 3)];
        ab2r[nt][1] = S->ab2s[cbase + nt * 8 + 2 * (l & 3) + 1];
    }

    const int wbase8 = w * 8;

    for (int it = 0; it < ITER; ++it) {
        const int blockBase = (blockIdx.x * ITER + it) * TILE_E;

        if (t < TILE_E) {
            int e = blockBase + t;
            int s = 0, g = 0, ms = -1; float pen = 0.f;
            if (e < E) {
                s = __ldcs(&edges[2 * e]); g = __ldcs(&edges[2 * e + 1]);
                int sa = army[s], ta = army[g];
                ms = sa - 1;
                if (sa <= 2 || ta >= 3 * sa) pen += 1.f;
                if (s == g) pen += 100.f;
            }
            S->srcOff[t] = (uint)s * 768u;
            S->tgtOff[t] = (uint)g * 768u;
            S->maxsend[t] = ms; S->pen[t] = pen;
        }
        __syncthreads();

        // Phase 1: 4 iterations x 2 edges/warp (lane halves), double-buffered.
        uint4 wsv[2], wtv[2];
        uint2 pav[2], ptv[2];
        {
            const int le = wbase8 + half;
            const uint sB = S->srcOff[le];
            const uint tB = S->tgtOff[le];
            wsv[0] = *(const uint4*)(projc + sB + f8 * 2);
            pav[0] = *(const uint2*)(projc + sB + 256 + f8);
            wtv[0] = *(const uint4*)(projc + tB + 384 + f8 * 2);
            ptv[0] = *(const uint2*)(projc + tB + 640 + f8);
        }

        #pragma unroll
        for (int i = 0; i < 4; ++i) {
            const int cur = i & 1, nxt = cur ^ 1;
            if (i < 3) {
                const int le = wbase8 + 2 * (i + 1) + half;
                const uint sB = S->srcOff[le];
                const uint tB = S->tgtOff[le];
                wsv[nxt] = *(const uint4*)(projc + sB + f8 * 2);
                pav[nxt] = *(const uint2*)(projc + sB + 256 + f8);
                wtv[nxt] = *(const uint4*)(projc + tB + 384 + f8 * 2);
                ptv[nxt] = *(const uint2*)(projc + tB + 640 + f8);
            }
            const int le = wbase8 + 2 * i + half;
            const int e  = blockBase + le;

            __half2 sw[4], tw[4];
            sw[0] = *(__half2*)&wsv[cur].x; sw[1] = *(__half2*)&wsv[cur].y;
            sw[2] = *(__half2*)&wsv[cur].z; sw[3] = *(__half2*)&wsv[cur].w;
            tw[0] = *(__half2*)&wtv[cur].x; tw[1] = *(__half2*)&wtv[cur].y;
            tw[2] = *(__half2*)&wtv[cur].z; tw[3] = *(__half2*)&wtv[cur].w;
            __half2 acc2 = zero2;
            #pragma unroll
            for (int q = 0; q < 4; ++q) {
                __half2 h = __hmax2(__hadd2(__hadd2(sw[q], tw[q]), b1h[q]), zero2);
                acc2 = __hfma2(h, w2h[q], acc2);
            }
            float2 pf = __half22float2(acc2);
            float part = pf.x + pf.y;
            #pragma unroll
            for (int d = 8; d > 0; d >>= 1)
                part += __shfl_xor_sync(0xffffffffu, part, d);
            if (fl == 0 && e < E) __stcs(&out[e], part + b2v - S->pen[le]);

            uint sa01, sa23, sa45, sa67, ta01, ta23, ta45, ta67;
            unpack_e4m3_4(pav[cur].x, sa01, sa23);
            unpack_e4m3_4(pav[cur].y, sa45, sa67);
            unpack_e4m3_4(ptv[cur].x, ta01, ta23);
            unpack_e4m3_4(ptv[cur].y, ta45, ta67);
            __half2 g0 = __hmax2(__hadd2(__hadd2(*(__half2*)&sa01, *(__half2*)&ta01), ab1h[0]), zero2);
            __half2 g1 = __hmax2(__hadd2(__hadd2(*(__half2*)&sa23, *(__half2*)&ta23), ab1h[1]), zero2);
            __half2 g2 = __hmax2(__hadd2(__hadd2(*(__half2*)&sa45, *(__half2*)&ta45), ab1h[2]), zero2);
            __half2 g3 = __hmax2(__hadd2(__hadd2(*(__half2*)&sa67, *(__half2*)&ta67), ab1h[3]), zero2);
            unsigned short q0 = cvt_f16x2_e4m3x2(*(uint*)&g0);
            unsigned short q1 = cvt_f16x2_e4m3x2(*(uint*)&g1);
            unsigned short q2 = cvt_f16x2_e4m3x2(*(uint*)&g2);
            unsigned short q3 = cvt_f16x2_e4m3x2(*(uint*)&g3);
            uint2 stv;
            asm("mov.b32 %0, {%1, %2};" : "=r"(stv.x) : "h"(q0), "h"(q1));
            asm("mov.b32 %0, {%1, %2};" : "=r"(stv.y) : "h"(q2), "h"(q3));
            *(uint2*)&S->ha[le][f8] = stv;
        }
        __syncthreads();

        // Phase 2: army GEMM, fp8 m16n8k32.
        float c[4][4];
        #pragma unroll
        for (int nt = 0; nt < 4; ++nt) {
            c[nt][0] = ab2r[nt][0]; c[nt][1] = ab2r[nt][1];
            c[nt][2] = ab2r[nt][0]; c[nt][3] = ab2r[nt][1];
        }

        #pragma unroll
        for (int ks = 0; ks < 4; ++ks) {
            const int kb = ks * 32;
            unsigned a0, a1, a2, a3;
            unsigned aaddr = haBase + (unsigned)(arow * 144 + kb + abyte);
            asm volatile("ldmatrix.sync.aligned.m8n8.x4.shared.b16 {%0,%1,%2,%3}, [%4];"
                         : "=r"(a0), "=r"(a1), "=r"(a2), "=r"(a3) : "r"(aaddr));
            #pragma unroll
            for (int g2i = 0; g2i < 2; ++g2i) {
                unsigned b0, b1r, b2r, b3r;
                unsigned baddr = a2Base + (unsigned)((cbase + g2i * 16 + bcol) * 144 + kb + bbyte);
                asm volatile("ldmatrix.sync.aligned.m8n8.x4.shared.b16 {%0,%1,%2,%3}, [%4];"
                             : "=r"(b0), "=r"(b1r), "=r"(b2r), "=r"(b3r) : "r"(baddr));
                asm volatile("mma.sync.aligned.m16n8k32.row.col.f32.e4m3.e4m3.f32 "
                             "{%0,%1,%2,%3},{%4,%5,%6,%7},{%8,%9},{%0,%1,%2,%3};"
                             : "+f"(c[2*g2i][0]), "+f"(c[2*g2i][1]), "+f"(c[2*g2i][2]), "+f"(c[2*g2i][3])
                             : "r"(a0), "r"(a1), "r"(a2), "r"(a3), "r"(b0), "r"(b2r));
                asm volatile("mma.sync.aligned.m16n8k32.row.col.f32.e4m3.e4m3.f32 "
                             "{%0,%1,%2,%3},{%4,%5,%6,%7},{%8,%9},{%0,%1,%2,%3};"
                             : "+f"(c[2*g2i+1][0]), "+f"(c[2*g2i+1][1]), "+f"(c[2*g2i+1][2]), "+f"(c[2*g2i+1][3])
                             : "r"(a0), "r"(a1), "r"(a2), "r"(a3), "r"(b1r), "r"(b3r));
            }
        }

        // Epilogue.
        const int r0 = wbase16 + (l >> 2);
        const int e0 = blockBase + r0;
        const int e1 = e0 + 8;
        const int ms0 = S->maxsend[r0];
        const int ms1 = S->maxsend[r0 + 8];
        #pragma unroll
        for (int nt = 0; nt < 4; ++nt) {
            const int col = cbase + nt * 8 + 2 * (l & 3);
            if (e0 < E) {
                float2 v;
                v.x = (col     <= ms0) ? c[nt][0] : -1.0e9f;
                v.y = (col + 1 <= ms0) ? c[nt][1] : -1.0e9f;
                __stcs((float2*)&out[(size_t)E + (size_t)e0 * 64 + col], v);
            }
            if (e1 < E) {
                float2 v;
                v.x = (col     <= ms1) ? c[nt][2] : -1.0e9f;
                v.y = (col + 1 <= ms1) ? c[nt][3] : -1.0e9f;
                __stcs((float2*)&out[(size_t)E + (size_t)e1 * 64 + col], v);
            }
        }
        __syncthreads();
    }
}

// ---------------------------------------------------------------- launch ----
extern "C" void kernel_launch(void* const* d_in, const int* in_sizes, int n_in,
                              void* d_out, int out_size)
{
    const float* emb   = (const float*)d_in[0];
    const int*   edges = (const int*)  d_in[1];
    const int*   army  = (const int*)  d_in[2];
    const float* W1    = (const float*)d_in[3];
    const float* b1    = (const float*)d_in[4];
    const float* W2    = (const float*)d_in[5];
    const float* b2    = (const float*)d_in[6];
    const float* A1    = (const float*)d_in[7];
    const float* ab1   = (const float*)d_in[8];
    const float* A2    = (const float*)d_in[9];
    const float* ab2   = (const float*)d_in[10];
    float* out = (float*)d_out;

    int N = in_sizes[0] / 128;
    int E = in_sizes[1] / 2;
    if (N > MAX_N) N = MAX_N;

    a2prep_kernel<<<1, 256>>>(A2, ab2);
    wprep_kernel<<<2, 256>>>(W1, A1);

    int nTiles = (N + 63) / 64;
    int g1 = nTiles < 304 ? nTiles : 304;   // ~2 blocks/SM persistent
    cudaFuncSetAttribute(precompute_kernel,
                         cudaFuncAttributeMaxDynamicSharedMemorySize, S1_TOTAL);
    precompute_kernel<<<g1, 256, S1_TOTAL>>>(emb, N, nTiles);

    cudaFuncSetAttribute(edge_kernel, cudaFuncAttributeMaxDynamicSharedMemorySize,
                         (int)sizeof(S2));
    int eblk = (E + TILE_E * ITER - 1) / (TILE_E * ITER);
    edge_kernel<<<eblk, 256, sizeof(S2)>>>(
        edges, army, b1, W2, b2, ab1, out, E);
}